// round 6
// baseline (speedup 1.0000x reference)
#include <cuda_runtime.h>
#include <cuda_fp16.h>

// HybridEulerIntegrator: a_{t+1} = a_t + C * (MLP([x_t, a_t]))^3
// MLP: 2 -> 64 (tanh) -> 1, hidden layer in packed f16x2, f32 recurrence state.
// TPE=16 lanes per element (4 hidden units / 2 half2 pairs per thread) ->
// 262144 threads, ~13.8 warps/SMSP: saturate the MUFU queue, hide the chain.

#define T_STEPS 2048
#define BATCH   16384
#define HIDDEN  64
#define TPE     16
#define PAIRS   2    // half2 pairs per thread (4 hidden units)
#define BLOCK   128
#define W2SCALE 0.125f

__device__ __forceinline__ __half2 tanh_h2(__half2 v) {
    unsigned r, in = *(unsigned*)&v;
    asm("tanh.approx.f16x2 %0, %1;" : "=r"(r) : "r"(in));
    return *(__half2*)&r;
}

__global__ void __launch_bounds__(BLOCK)
hybrid_euler_kernel(const float* __restrict__ x,
                    const float* __restrict__ a0,
                    const float* __restrict__ W1,
                    const float* __restrict__ b1,
                    const float* __restrict__ W2,
                    const float* __restrict__ b2,
                    float* __restrict__ out)
{
    const int tid = blockIdx.x * BLOCK + threadIdx.x;
    const int e   = tid >> 4;        // element index
    const int s   = tid & 15;        // sub-lane within 16-lane group

    // This thread's 4 hidden units as 2 half2 pairs (loop-invariant registers).
    __half2 w1x[PAIRS], w1a[PAIRS], b1h[PAIRS], w2h[PAIRS];
#pragma unroll
    for (int p = 0; p < PAIRS; p++) {
        const int j = s * (2 * PAIRS) + 2 * p;
        w1x[p] = __floats2half2_rn(W1[j],           W1[j + 1]);
        w1a[p] = __floats2half2_rn(W1[HIDDEN + j],  W1[HIDDEN + j + 1]);
        b1h[p] = __floats2half2_rn(b1[j],           b1[j + 1]);
        w2h[p] = __floats2half2_rn(W2[j] * W2SCALE, W2[j + 1] * W2SCALE);
    }
    const float bias2 = b2[0];

    float a = a0[e];
    const float* xp = x + e;
    float*       op = out + e;

    // Prologue: x_0 contribution to pre-activations (independent of a).
    __half2 xpart[PAIRS];
    {
        const __half2 xh0 = __float2half2_rn(__ldg(xp));
#pragma unroll
        for (int p = 0; p < PAIRS; p++)
            xpart[p] = __hfma2(xh0, w1x[p], b1h[p]);
    }

    for (int t = 0; t < T_STEPS; t++) {
        // Pipelined load of x_{t+1} (off the a-chain).
        float xt_next = 0.0f;
        if (t + 1 < T_STEPS) xt_next = __ldg(xp + BATCH);
        xp += BATCH;

        const __half2 ah = __float2half2_rn(a);

        // Critical chain: ah -> HFMA2 -> tanh -> acc (2 independent chains).
        __half2 pre0 = __hfma2(ah, w1a[0], xpart[0]);
        __half2 pre1 = __hfma2(ah, w1a[1], xpart[1]);
        __half2 acc0 = __hmul2(tanh_h2(pre0), w2h[0]);
        __half2 acc1 = __hmul2(tanh_h2(pre1), w2h[1]);

        // Off-chain: next step's x-part while the chain drains.
        const __half2 xhn = __float2half2_rn(xt_next);
#pragma unroll
        for (int p = 0; p < PAIRS; p++)
            xpart[p] = __hfma2(xhn, w1x[p], b1h[p]);

        const __half2 accs = __hadd2(acc0, acc1);
        const float2 f2 = __half22float2(accs);
        float dk = f2.x + f2.y;

        // Butterfly reduce across the 16 lanes of this element's group.
        dk += __shfl_xor_sync(0xFFFFFFFFu, dk, 1);
        dk += __shfl_xor_sync(0xFFFFFFFFu, dk, 2);
        dk += __shfl_xor_sync(0xFFFFFFFFu, dk, 4);
        dk += __shfl_xor_sync(0xFFFFFFFFu, dk, 8);
        dk = fmaf(dk, 8.0f, bias2);   // undo W2SCALE, add output bias

        // a += C * dk^3
        const float dk2 = dk * dk;
        a = fmaf(0.001f * dk, dk2, a);

        if (s == 0) *op = a;
        op += BATCH;
    }
}

extern "C" void kernel_launch(void* const* d_in, const int* in_sizes, int n_in,
                              void* d_out, int out_size)
{
    const float* x  = (const float*)d_in[0];
    const float* a0 = (const float*)d_in[1];
    const float* W1 = (const float*)d_in[2];
    const float* b1 = (const float*)d_in[3];
    const float* W2 = (const float*)d_in[4];
    const float* b2 = (const float*)d_in[5];
    float* out = (float*)d_out;

    const int total_threads = BATCH * TPE;           // 262144
    const int grid = total_threads / BLOCK;          // 2048 blocks of 4 warps
    hybrid_euler_kernel<<<grid, BLOCK>>>(x, a0, W1, b1, W2, b2, out);
}